// round 5
// baseline (speedup 1.0000x reference)
#include <cuda_runtime.h>
#include <cuda_bf16.h>
#include <cstdint>

#define BATCH 4
#define CDIM  64
#define NTOK  4096
#define KSEL  1024

typedef unsigned long long u64;

__device__ float g_q[BATCH * NTOK * CDIM];          // (b, n, c)  pre-scaled
__device__ float g_k[BATCH * CDIM * NTOK];          // (b, c, m)
__device__ float g_v[BATCH * NTOK * CDIM];          // (b, m, c)
__device__ float g_s[BATCH * NTOK * NTOK];          // (b, n, m) fp32 scores
__device__ __nv_bfloat16 g_p[BATCH * NTOK * NTOK];  // (b, n, m) bf16 probabilities
__device__ float g_o[BATCH * CDIM * NTOK];          // (b, c, n)

union F4P { float4 f; u64 p[2]; };

__device__ __forceinline__ u64 pk(float x, float y) {
    u64 r; asm("mov.b64 %0, {%1, %2};" : "=l"(r) : "f"(x), "f"(y)); return r;
}
__device__ __forceinline__ void fma2(u64& d, u64 a, u64 b) {
    asm("fma.rn.f32x2 %0, %1, %2, %0;" : "+l"(d) : "l"(a), "l"(b));
}
__device__ __forceinline__ void unpk(u64 v, float& lo, float& hi) {
    asm("mov.b64 {%0, %1}, %2;" : "=f"(lo), "=f"(hi) : "l"(v));
}
__device__ __forceinline__ unsigned pack_bf16x2(float hi, float lo) {
    unsigned r;
    asm("cvt.rn.bf16x2.f32 %0, %1, %2;" : "=r"(r) : "f"(hi), "f"(lo));
    return r;
}
// order-preserving float->uint and inverse
__device__ __forceinline__ unsigned f2u(unsigned ub) {
    return (int)ub < 0 ? ~ub : (ub | 0x80000000u);
}
__device__ __forceinline__ float u2f(unsigned u) {
    unsigned ub = (int)u < 0 ? (u ^ 0x80000000u) : ~u;
    return __uint_as_float(ub);
}

// ---------------- kernel 0: zero g_o ----------------
__global__ __launch_bounds__(256) void zero_o_kernel()
{
    int i = blockIdx.x * 256 + threadIdx.x;
    ((float4*)g_o)[i] = make_float4(0.f, 0.f, 0.f, 0.f);
}

// ---------------- kernel 1: fused QKV projection ----------------
__global__ __launch_bounds__(256) void qkv_kernel(const float* __restrict__ x,
                                                  const float* __restrict__ skip,
                                                  const float* __restrict__ w_qkv)
{
    __shared__ float sx[64][64];
    __shared__ float ss[64][64];
    const int b  = blockIdx.y;
    const int n0 = blockIdx.x * 64;
    const int t  = threadIdx.x;

    for (int idx = t; idx < 64 * 64; idx += 256) {
        int c = idx >> 6, j = idx & 63;
        sx[c][j] = x[((b * 64 + c) << 12) + n0 + j];
        ss[c][j] = skip[((b * 64 + c) << 12) + n0 + j];
    }
    __syncthreads();

    const float scale = 0.125f;
    for (int r = 0; r < 48; r++) {
        int outIdx = t + (r << 8);
        int sel = outIdx >> 12;
        int rem = outIdx & 4095;
        int o = rem >> 6, j = rem & 63;
        const float* wrow = w_qkv + ((sel << 6) + o) * 64;
        float acc = 0.f;
        if (sel == 0) {
            #pragma unroll
            for (int c = 0; c < 64; c++) acc += wrow[c] * sx[c][j];
            g_q[(((b << 12) + n0 + j) << 6) + o] = acc * scale;
        } else {
            #pragma unroll
            for (int c = 0; c < 64; c++) acc += wrow[c] * ss[c][j];
            if (sel == 1) g_k[(((b << 6) + o) << 12) + n0 + j] = acc;
            else          g_v[(((b << 12) + n0 + j) << 6) + o] = acc;
        }
    }
}

// ---------------- kernel 2: S = Q @ K, 64n x 128m tile, f32x2 ----------------
__global__ __launch_bounds__(256) void scores_kernel()
{
    __shared__ float sQ[64][64];
    __shared__ float sK[64][128];
    const int b  = blockIdx.z;
    const int n0 = blockIdx.y * 64;
    const int m0 = blockIdx.x * 128;
    const int t  = threadIdx.x;
    const int tx = t & 15, ty = t >> 4;

    #pragma unroll
    for (int k = 0; k < 4; k++) {
        int idx = t + k * 256;
        int r = idx >> 4, c4 = idx & 15;
        *(float4*)&sQ[r][c4 * 4] = *(const float4*)&g_q[(((b << 12) + n0 + r) << 6) + c4 * 4];
    }
    #pragma unroll
    for (int k = 0; k < 8; k++) {
        int idx = t + k * 256;
        int r = idx >> 5, c4 = idx & 31;
        *(float4*)&sK[r][c4 * 4] = *(const float4*)&g_k[(((b << 6) + r) << 12) + m0 + c4 * 4];
    }
    __syncthreads();

    u64 acc[4][4];
    #pragma unroll
    for (int i = 0; i < 4; i++)
        #pragma unroll
        for (int j = 0; j < 4; j++) acc[i][j] = 0ull;

    #pragma unroll 8
    for (int c = 0; c < 64; c++) {
        F4P b0, b1;
        b0.f = *(float4*)&sK[c][tx * 8];
        b1.f = *(float4*)&sK[c][tx * 8 + 4];
        #pragma unroll
        for (int i = 0; i < 4; i++) {
            float a = sQ[ty * 4 + i][c];
            u64 ap = pk(a, a);
            fma2(acc[i][0], ap, b0.p[0]);
            fma2(acc[i][1], ap, b0.p[1]);
            fma2(acc[i][2], ap, b1.p[0]);
            fma2(acc[i][3], ap, b1.p[1]);
        }
    }

    #pragma unroll
    for (int i = 0; i < 4; i++) {
        size_t base = ((size_t)b << 24) + (size_t)(n0 + ty * 4 + i) * NTOK + m0 + tx * 8;
        F4P o0, o1;
        o0.p[0] = acc[i][0]; o0.p[1] = acc[i][1];
        o1.p[0] = acc[i][2]; o1.p[1] = acc[i][3];
        *(float4*)&g_s[base]     = o0.f;
        *(float4*)&g_s[base + 4] = o1.f;
    }
}

// ---------------- kernel 3: exact top-k threshold + masked softmax -> bf16 ----------------
__global__ __launch_bounds__(256) void select_softmax_kernel()
{
    const int row = blockIdx.x;
    const int b = row >> 12, n = row & 4095;
    const size_t base = ((size_t)b << 24) + (size_t)n * NTOK;
    const int t = threadIdx.x;
    const int wid = t >> 5, lane = t & 31;

    __shared__ int hist8[8][256];            // 8 KB
    __shared__ unsigned candA[4096];         // 16 KB
    __shared__ unsigned short candB[4096];   // 8 KB
    __shared__ int warpTot[8];
    __shared__ int sh_cntA, sh_cntB;
    __shared__ unsigned sh_bin;
    __shared__ int sh_kk;
    __shared__ unsigned sh_maxu;
    __shared__ float sh_z;

    if (t == 0) { sh_maxu = 0u; sh_z = 0.f; sh_cntA = 0; sh_cntB = 0; }
    #pragma unroll
    for (int w = 0; w < 8; w++) hist8[w][t] = 0;
    __syncthreads();

    // load 16 contiguous values, keep only transformed keys in regs
    unsigned uv[16];
    const size_t myb = base + (size_t)t * 16;
    #pragma unroll
    for (int k = 0; k < 4; k++) {
        float4 f = *(const float4*)&g_s[myb + k * 4];
        uv[k * 4 + 0] = f2u(__float_as_uint(f.x));
        uv[k * 4 + 1] = f2u(__float_as_uint(f.y));
        uv[k * 4 + 2] = f2u(__float_as_uint(f.z));
        uv[k * 4 + 3] = f2u(__float_as_uint(f.w));
    }
    unsigned my_maxu = 0u;
    #pragma unroll
    for (int i = 0; i < 16; i++) my_maxu = my_maxu > uv[i] ? my_maxu : uv[i];
    #pragma unroll
    for (int off = 16; off; off >>= 1) {
        unsigned o = __shfl_xor_sync(0xffffffffu, my_maxu, off);
        my_maxu = my_maxu > o ? my_maxu : o;
    }
    if (lane == 0) atomicMax(&sh_maxu, my_maxu);

    // ---- pass 1 (bits 31:24): match-aggregated per-warp histograms ----
    int* myh = hist8[wid];
    #pragma unroll
    for (int i = 0; i < 16; i++) {
        unsigned bin = uv[i] >> 24;
        unsigned mk = __match_any_sync(0xffffffffu, bin);
        if (lane == (__ffs(mk) - 1)) atomicAdd(&myh[bin], __popc(mk));
    }
    __syncthreads();

    int tot = 0;
    #pragma unroll
    for (int w = 0; w < 8; w++) tot += hist8[w][t];
    int v = tot;
    #pragma unroll
    for (int off = 1; off < 32; off <<= 1) {
        int o = __shfl_down_sync(0xffffffffu, v, off);
        if (lane + off < 32) v += o;
    }
    if (lane == 0) warpTot[wid] = v;
    __syncthreads();
    int above = 0;
    #pragma unroll
    for (int w = 0; w < 8; w++) if (w > wid) above += warpTot[w];
    int cum_incl = v + above, cum_excl = cum_incl - tot;
    if (cum_excl < KSEL && KSEL <= cum_incl) { sh_bin = (unsigned)t; sh_kk = KSEL - cum_excl; }
    __syncthreads();
    unsigned bin1 = sh_bin;
    int kk = sh_kk;

    // compact matching candidates into candA; re-zero histograms for pass 2
    {
        int cnt = 0;
        #pragma unroll
        for (int i = 0; i < 16; i++) cnt += ((uv[i] >> 24) == bin1);
        int pos = 0;
        if (cnt) pos = atomicAdd(&sh_cntA, cnt);
        #pragma unroll
        for (int i = 0; i < 16; i++)
            if ((uv[i] >> 24) == bin1) candA[pos++] = uv[i];
    }
    #pragma unroll
    for (int w = 0; w < 8; w++) hist8[w][t] = 0;
    __syncthreads();
    int ncand = sh_cntA;

    // ---- pass 2 (bits 23:16) over candA ----
    for (int i = t; i < ncand; i += 256)
        atomicAdd(&hist8[wid][(candA[i] >> 16) & 255], 1);
    __syncthreads();
    tot = 0;
    #pragma unroll
    for (int w = 0; w < 8; w++) tot += hist8[w][t];
    v = tot;
    #pragma unroll
    for (int off = 1; off < 32; off <<= 1) {
        int o = __shfl_down_sync(0xffffffffu, v, off);
        if (lane + off < 32) v += o;
    }
    if (lane == 0) warpTot[wid] = v;
    __syncthreads();
    above = 0;
    #pragma unroll
    for (int w = 0; w < 8; w++) if (w > wid) above += warpTot[w];
    cum_incl = v + above; cum_excl = cum_incl - tot;
    if (cum_excl < kk && kk <= cum_incl) { sh_bin = (unsigned)t; sh_kk = kk - cum_excl; }
    __syncthreads();
    unsigned bin2 = sh_bin;
    kk = sh_kk;

    // compact survivors (share top 16 bits) into candB as low-16 keys
    for (int i = t; i < ncand; i += 256) {
        unsigned u = candA[i];
        if (((u >> 16) & 255) == bin2)
            candB[atomicAdd(&sh_cntB, 1)] = (unsigned short)(u & 0xffffu);
    }
    hist8[0][t] = 0;
    __syncthreads();
    int ncand2 = sh_cntB;

    // ---- pass 3 (bits 15:8) over candB ----
    for (int i = t; i < ncand2; i += 256)
        atomicAdd(&hist8[0][candB[i] >> 8], 1);
    __syncthreads();
    tot = hist8[0][t];
    v = tot;
    #pragma unroll
    for (int off = 1; off < 32; off <<= 1) {
        int o = __shfl_down_sync(0xffffffffu, v, off);
        if (lane + off < 32) v += o;
    }
    if (lane == 0) warpTot[wid] = v;
    __syncthreads();
    above = 0;
    #pragma unroll
    for (int w = 0; w < 8; w++) if (w > wid) above += warpTot[w];
    cum_incl = v + above; cum_excl = cum_incl - tot;
    if (cum_excl < kk && kk <= cum_incl) { sh_bin = (unsigned)t; sh_kk = kk - cum_excl; }
    __syncthreads();
    unsigned bin3 = sh_bin;
    kk = sh_kk;
    hist8[0][t] = 0;
    __syncthreads();

    // ---- pass 4 (bits 7:0) over candB, predicated on bin3 ----
    for (int i = t; i < ncand2; i += 256) {
        unsigned u = candB[i];
        if ((u >> 8) == bin3) atomicAdd(&hist8[0][u & 255], 1);
    }
    __syncthreads();
    tot = hist8[0][t];
    v = tot;
    #pragma unroll
    for (int off = 1; off < 32; off <<= 1) {
        int o = __shfl_down_sync(0xffffffffu, v, off);
        if (lane + off < 32) v += o;
    }
    if (lane == 0) warpTot[wid] = v;
    __syncthreads();
    above = 0;
    #pragma unroll
    for (int w = 0; w < 8; w++) if (w > wid) above += warpTot[w];
    cum_incl = v + above; cum_excl = cum_incl - tot;
    if (cum_excl < kk && kk <= cum_incl) sh_bin = (unsigned)t;
    __syncthreads();

    unsigned prefix = (bin1 << 24) | (bin2 << 16) | (bin3 << 8) | sh_bin;

    // decode threshold + max, masked softmax
    float thr  = u2f(prefix);
    float smax = u2f(sh_maxu);
    float M = fmaxf(smax, 0.f);
    float expM = __expf(-M);

    float w[16];
    float zloc = 0.f;
    #pragma unroll
    for (int i = 0; i < 16; i++) {
        float val = u2f(uv[i]);
        float wv = (val >= thr) ? __expf(val - M) : expM;
        w[i] = wv;
        zloc += wv;
    }
    #pragma unroll
    for (int off = 16; off; off >>= 1) zloc += __shfl_xor_sync(0xffffffffu, zloc, off);
    if (lane == 0) atomicAdd(&sh_z, zloc);
    __syncthreads();

    float invZ = 1.f / sh_z;
    #pragma unroll
    for (int h = 0; h < 2; h++) {
        uint4 o;
        o.x = pack_bf16x2(w[h*8+1] * invZ, w[h*8+0] * invZ);
        o.y = pack_bf16x2(w[h*8+3] * invZ, w[h*8+2] * invZ);
        o.z = pack_bf16x2(w[h*8+5] * invZ, w[h*8+4] * invZ);
        o.w = pack_bf16x2(w[h*8+7] * invZ, w[h*8+6] * invZ);
        *(uint4*)&g_p[myb + h * 8] = o;
    }
}

// ---------------- kernel 4: O(n,c) = P(n,m) x Vt(m,c), split-K, f32x2, bf16 P ----------------
__global__ __launch_bounds__(256) void av_kernel()
{
    __shared__ u64  sPd[128][17];
    __shared__ float sV[16][64];
    const int b     = blockIdx.z;
    const int chunk = blockIdx.y;
    const int n0    = blockIdx.x * 128;
    const int t  = threadIdx.x;
    const int tx = t & 7, ty = t >> 3;     // tx -> c (8 each), ty -> n (4 each)
    const size_t bbase = ((size_t)b << 24);

    u64 acc[4][4];
    #pragma unroll
    for (int i = 0; i < 4; i++)
        #pragma unroll
        for (int j = 0; j < 4; j++) acc[i][j] = 0ull;

    for (int mt = 0; mt < 32; mt++) {
        int mbase = chunk * 512 + mt * 16;
        {
            int r = t >> 1, h = t & 1;
            uint4 raw = *(const uint4*)&g_p[bbase + (size_t)(n0 + r) * NTOK + mbase + h * 8];
            unsigned uw[4] = {raw.x, raw.y, raw.z, raw.w};
            #pragma unroll
            for (int j = 0; j < 4; j++) {
                float flo = __uint_as_float(uw[j] << 16);
                float fhi = __uint_as_float(uw[j] & 0xffff0000u);
                sPd[r][h * 8 + j * 2 + 0] = pk(flo, flo);
                sPd[r][h * 8 + j * 2 + 1] = pk(fhi, fhi);
            }
        }
        {
            int r = t >> 4, c4 = t & 15;
            *(float4*)&sV[r][c4 * 4] = *(const float4*)&g_v[(((b << 12) + mbase + r) << 6) + c4 * 4];
        }
        __syncthreads();

        #pragma unroll
        for (int m = 0; m < 16; m++) {
            F4P bv0, bv1;
            bv0.f = *(float4*)&sV[m][tx * 8];
            bv1.f = *(float4*)&sV[m][tx * 8 + 4];
            #pragma unroll
            for (int i = 0; i < 4; i++) {
                u64 ap = sPd[ty * 4 + i][m];
                fma2(acc[i][0], ap, bv0.p[0]);
                fma2(acc[i][1], ap, bv0.p[1]);
                fma2(acc[i][2], ap, bv1.p[0]);
                fma2(acc[i][3], ap, bv1.p[1]);
            }
        }
        __syncthreads();
    }

    #pragma unroll
    for (int i = 0; i < 4; i++) {
        int nn = n0 + ty * 4 + i;
        #pragma unroll
        for (int j = 0; j < 4; j++) {
            float lo, hi;
            unpk(acc[i][j], lo, hi);
            int c0 = tx * 8 + j * 2;
            atomicAdd(&g_o[(size_t)(((b << 6) + c0) << 12) + nn], lo);
            atomicAdd(&g_o[(size_t)(((b << 6) + c0 + 1) << 12) + nn], hi);
        }
    }
}

// ---------------- kernel 5: output projection + bias + residual ----------------
__global__ __launch_bounds__(256) void proj_kernel(const float* __restrict__ x,
                                                   const float* __restrict__ w_out,
                                                   const float* __restrict__ b_out,
                                                   const float* __restrict__ gamma,
                                                   float* __restrict__ out)
{
    __shared__ float sT[64][64];
    const int b  = blockIdx.y;
    const int n0 = blockIdx.x * 64;
    const int t  = threadIdx.x;

    for (int idx = t; idx < 64 * 64; idx += 256) {
        int c = idx >> 6, j = idx & 63;
        sT[c][j] = g_o[(((b << 6) + c) << 12) + n0 + j];
    }
    __syncthreads();

    const float g = gamma[0];
    for (int r = 0; r < 16; r++) {
        int outIdx = t + (r << 8);
        int o = outIdx >> 6, j = outIdx & 63;
        const float* wrow = w_out + o * 64;
        float acc = b_out[o];
        #pragma unroll
        for (int c = 0; c < 64; c++) acc += wrow[c] * sT[c][j];
        size_t gi = (size_t)(((b << 6) + o) << 12) + n0 + j;
        out[gi] = g * acc + x[gi];
    }
}

// ---------------- launch ----------------
extern "C" void kernel_launch(void* const* d_in, const int* in_sizes, int n_in,
                              void* d_out, int out_size)
{
    const float* x     = (const float*)d_in[0];
    const float* skip  = (const float*)d_in[1];
    const float* w_qkv = (const float*)d_in[2];
    const float* w_out = (const float*)d_in[3];
    const float* b_out = (const float*)d_in[4];
    const float* gamma = (const float*)d_in[5];
    float* out = (float*)d_out;

    zero_o_kernel<<<1024, 256>>>();
    qkv_kernel<<<dim3(64, BATCH), 256>>>(x, skip, w_qkv);
    scores_kernel<<<dim3(32, 64, BATCH), 256>>>();
    select_softmax_kernel<<<BATCH * NTOK, 256>>>();
    av_kernel<<<dim3(32, 8, BATCH), 256>>>();
    proj_kernel<<<dim3(64, BATCH), 256>>>(x, w_out, b_out, gamma, out);
}

// round 6
// speedup vs baseline: 1.2190x; 1.2190x over previous
#include <cuda_runtime.h>
#include <cuda_bf16.h>
#include <cstdint>

#define BATCH 4
#define CDIM  64
#define NTOK  4096
#define KSEL  1024

typedef unsigned long long u64;

__device__ float g_q[BATCH * NTOK * CDIM];          // (b, n, c)  pre-scaled
__device__ float g_k[BATCH * CDIM * NTOK];          // (b, c, m)
__device__ float g_v[BATCH * NTOK * CDIM];          // (b, m, c)
__device__ float g_s[BATCH * NTOK * NTOK];          // (b, n, m) fp32 scores
__device__ __nv_bfloat16 g_p[BATCH * NTOK * NTOK];  // (b, n, m) bf16 probabilities
__device__ float g_o[BATCH * CDIM * NTOK];          // (b, c, n)

union F4P { float4 f; u64 p[2]; };

__device__ __forceinline__ u64 pk(float x, float y) {
    u64 r; asm("mov.b64 %0, {%1, %2};" : "=l"(r) : "f"(x), "f"(y)); return r;
}
__device__ __forceinline__ void fma2(u64& d, u64 a, u64 b) {
    asm("fma.rn.f32x2 %0, %1, %2, %0;" : "+l"(d) : "l"(a), "l"(b));
}
__device__ __forceinline__ void unpk(u64 v, float& lo, float& hi) {
    asm("mov.b64 {%0, %1}, %2;" : "=f"(lo), "=f"(hi) : "l"(v));
}
__device__ __forceinline__ unsigned pack_bf16x2(float hi, float lo) {
    unsigned r;
    asm("cvt.rn.bf16x2.f32 %0, %1, %2;" : "=r"(r) : "f"(hi), "f"(lo));
    return r;
}

// ---------------- kernel 0: zero g_o ----------------
__global__ __launch_bounds__(256) void zero_o_kernel()
{
    int i = blockIdx.x * 256 + threadIdx.x;
    ((float4*)g_o)[i] = make_float4(0.f, 0.f, 0.f, 0.f);
}

// ---------------- kernel 1: fused QKV projection ----------------
__global__ __launch_bounds__(256) void qkv_kernel(const float* __restrict__ x,
                                                  const float* __restrict__ skip,
                                                  const float* __restrict__ w_qkv)
{
    __shared__ float sx[64][64];
    __shared__ float ss[64][64];
    const int b  = blockIdx.y;
    const int n0 = blockIdx.x * 64;
    const int t  = threadIdx.x;

    for (int idx = t; idx < 64 * 64; idx += 256) {
        int c = idx >> 6, j = idx & 63;
        sx[c][j] = x[((b * 64 + c) << 12) + n0 + j];
        ss[c][j] = skip[((b * 64 + c) << 12) + n0 + j];
    }
    __syncthreads();

    const float scale = 0.125f;
    for (int r = 0; r < 48; r++) {
        int outIdx = t + (r << 8);
        int sel = outIdx >> 12;
        int rem = outIdx & 4095;
        int o = rem >> 6, j = rem & 63;
        const float* wrow = w_qkv + ((sel << 6) + o) * 64;
        float acc = 0.f;
        if (sel == 0) {
            #pragma unroll
            for (int c = 0; c < 64; c++) acc += wrow[c] * sx[c][j];
            g_q[(((b << 12) + n0 + j) << 6) + o] = acc * scale;
        } else {
            #pragma unroll
            for (int c = 0; c < 64; c++) acc += wrow[c] * ss[c][j];
            if (sel == 1) g_k[(((b << 6) + o) << 12) + n0 + j] = acc;
            else          g_v[(((b << 12) + n0 + j) << 6) + o] = acc;
        }
    }
}

// ---------------- kernel 2: S = Q @ K, 64n x 128m tile, f32x2 ----------------
__global__ __launch_bounds__(256) void scores_kernel()
{
    __shared__ float sQ[64][64];
    __shared__ float sK[64][128];
    const int b  = blockIdx.z;
    const int n0 = blockIdx.y * 64;
    const int m0 = blockIdx.x * 128;
    const int t  = threadIdx.x;
    const int tx = t & 15, ty = t >> 4;

    #pragma unroll
    for (int k = 0; k < 4; k++) {
        int idx = t + k * 256;
        int r = idx >> 4, c4 = idx & 15;
        *(float4*)&sQ[r][c4 * 4] = *(const float4*)&g_q[(((b << 12) + n0 + r) << 6) + c4 * 4];
    }
    #pragma unroll
    for (int k = 0; k < 8; k++) {
        int idx = t + k * 256;
        int r = idx >> 5, c4 = idx & 31;
        *(float4*)&sK[r][c4 * 4] = *(const float4*)&g_k[(((b << 6) + r) << 12) + m0 + c4 * 4];
    }
    __syncthreads();

    u64 acc[4][4];
    #pragma unroll
    for (int i = 0; i < 4; i++)
        #pragma unroll
        for (int j = 0; j < 4; j++) acc[i][j] = 0ull;

    #pragma unroll 8
    for (int c = 0; c < 64; c++) {
        F4P b0, b1;
        b0.f = *(float4*)&sK[c][tx * 8];
        b1.f = *(float4*)&sK[c][tx * 8 + 4];
        #pragma unroll
        for (int i = 0; i < 4; i++) {
            float a = sQ[ty * 4 + i][c];
            u64 ap = pk(a, a);
            fma2(acc[i][0], ap, b0.p[0]);
            fma2(acc[i][1], ap, b0.p[1]);
            fma2(acc[i][2], ap, b1.p[0]);
            fma2(acc[i][3], ap, b1.p[1]);
        }
    }

    #pragma unroll
    for (int i = 0; i < 4; i++) {
        size_t base = ((size_t)b << 24) + (size_t)(n0 + ty * 4 + i) * NTOK + m0 + tx * 8;
        F4P o0, o1;
        o0.p[0] = acc[i][0]; o0.p[1] = acc[i][1];
        o1.p[0] = acc[i][2]; o1.p[1] = acc[i][3];
        *(float4*)&g_s[base]     = o0.f;
        *(float4*)&g_s[base + 4] = o1.f;
    }
}

// ---------------- kernel 3: value-histogram top-k threshold + masked softmax -> bf16 ----------------
__global__ __launch_bounds__(256) void select_softmax_kernel()
{
    const int row = blockIdx.x;
    const int b = row >> 12, n = row & 4095;
    const size_t base = ((size_t)b << 24) + (size_t)n * NTOK;
    const int t = threadIdx.x;
    const int wid = t >> 5, lane = t & 31;

    __shared__ int hist8[8][256];    // 8 KB
    __shared__ float candF[4096];    // 16 KB (worst case; typical use ~50)
    __shared__ float warpMax[8], warpMin[8];
    __shared__ int warpTot[8];
    __shared__ int sh_cnt;
    __shared__ int sh_bin, sh_kk;
    __shared__ float sh_thr, sh_z;

    if (t == 0) { sh_cnt = 0; sh_z = 0.f; }
    #pragma unroll
    for (int w = 0; w < 8; w++) hist8[w][t] = 0;

    // load 16 contiguous values per thread
    float vals[16];
    const size_t myb = base + (size_t)t * 16;
    #pragma unroll
    for (int k = 0; k < 4; k++) {
        float4 f = *(const float4*)&g_s[myb + k * 4];
        vals[k * 4 + 0] = f.x; vals[k * 4 + 1] = f.y;
        vals[k * 4 + 2] = f.z; vals[k * 4 + 3] = f.w;
    }

    // row min / max via shfl + tiny smem combine
    float mymax = vals[0], mymin = vals[0];
    #pragma unroll
    for (int i = 1; i < 16; i++) {
        mymax = fmaxf(mymax, vals[i]);
        mymin = fminf(mymin, vals[i]);
    }
    #pragma unroll
    for (int off = 16; off; off >>= 1) {
        mymax = fmaxf(mymax, __shfl_xor_sync(0xffffffffu, mymax, off));
        mymin = fminf(mymin, __shfl_xor_sync(0xffffffffu, mymin, off));
    }
    if (lane == 0) { warpMax[wid] = mymax; warpMin[wid] = mymin; }
    __syncthreads();
    float rmax = warpMax[0], rmin = warpMin[0];
    #pragma unroll
    for (int w = 1; w < 8; w++) {
        rmax = fmaxf(rmax, warpMax[w]);
        rmin = fminf(rmin, warpMin[w]);
    }

    // linear binning: monotone map value -> [0,255]
    float range = rmax - rmin;
    float scale = 256.0f / (range + 1e-30f) * (1.0f - 1e-6f);
    int* myh = hist8[wid];
    int bins[16];
    #pragma unroll
    for (int i = 0; i < 16; i++) {
        int bin = (int)((vals[i] - rmin) * scale);
        bin = bin < 0 ? 0 : (bin > 255 ? 255 : bin);
        bins[i] = bin;
        atomicAdd(&myh[bin], 1);
    }
    __syncthreads();

    // suffix scan over bins (bin index = t): find bin containing KSEL-th largest
    int tot = 0;
    #pragma unroll
    for (int w = 0; w < 8; w++) tot += hist8[w][t];
    int v = tot;
    #pragma unroll
    for (int off = 1; off < 32; off <<= 1) {
        int o = __shfl_down_sync(0xffffffffu, v, off);
        if (lane + off < 32) v += o;
    }
    if (lane == 0) warpTot[wid] = v;
    __syncthreads();
    int above = 0;
    #pragma unroll
    for (int w = 0; w < 8; w++) if (w > wid) above += warpTot[w];
    int cum_incl = v + above, cum_excl = cum_incl - tot;
    if (cum_excl < KSEL && KSEL <= cum_incl) { sh_bin = t; sh_kk = KSEL - cum_excl; }
    __syncthreads();
    const int selbin = sh_bin;
    const int kk = sh_kk;

    // compact candidates in selected bin
    {
        int cnt = 0;
        #pragma unroll
        for (int i = 0; i < 16; i++) cnt += (bins[i] == selbin);
        int pos = 0;
        if (cnt) pos = atomicAdd(&sh_cnt, cnt);
        #pragma unroll
        for (int i = 0; i < 16; i++)
            if (bins[i] == selbin) candF[pos++] = vals[i];
    }
    __syncthreads();
    const int ncand = sh_cnt;

    // exact rank among candidates: thr = kk-th largest in candF
    for (int i = t; i < ncand; i += 256) {
        float x = candF[i];
        int gt = 0, eq = 0;
        for (int j = 0; j < ncand; j++) {
            float y = candF[j];
            gt += (y > x);
            eq += (y == x);
        }
        if (gt < kk && kk <= gt + eq) sh_thr = x;
    }
    __syncthreads();

    const float thr = sh_thr;
    const float M = fmaxf(rmax, 0.f);
    const float expM = __expf(-M);

    float w[16];
    float zloc = 0.f;
    #pragma unroll
    for (int i = 0; i < 16; i++) {
        float wv = (vals[i] >= thr) ? __expf(vals[i] - M) : expM;
        w[i] = wv;
        zloc += wv;
    }
    #pragma unroll
    for (int off = 16; off; off >>= 1) zloc += __shfl_xor_sync(0xffffffffu, zloc, off);
    if (lane == 0) atomicAdd(&sh_z, zloc);
    __syncthreads();

    float invZ = 1.f / sh_z;
    #pragma unroll
    for (int h = 0; h < 2; h++) {
        uint4 o;
        o.x = pack_bf16x2(w[h*8+1] * invZ, w[h*8+0] * invZ);
        o.y = pack_bf16x2(w[h*8+3] * invZ, w[h*8+2] * invZ);
        o.z = pack_bf16x2(w[h*8+5] * invZ, w[h*8+4] * invZ);
        o.w = pack_bf16x2(w[h*8+7] * invZ, w[h*8+6] * invZ);
        *(uint4*)&g_p[myb + h * 8] = o;
    }
}

// ---------------- kernel 4: O(n,c) = P(n,m) x Vt(m,c), split-K, f32x2, bf16 P ----------------
__global__ __launch_bounds__(256) void av_kernel()
{
    __shared__ u64  sPd[128][17];
    __shared__ float sV[16][64];
    const int b     = blockIdx.z;
    const int chunk = blockIdx.y;
    const int n0    = blockIdx.x * 128;
    const int t  = threadIdx.x;
    const int tx = t & 15, ty = t >> 4;    // tx -> c (4 each), ty -> n (8 each)
    const size_t bbase = ((size_t)b << 24);

    u64 acc[8][2];
    #pragma unroll
    for (int i = 0; i < 8; i++) { acc[i][0] = 0ull; acc[i][1] = 0ull; }

    for (int mt = 0; mt < 32; mt++) {
        int mbase = chunk * 512 + mt * 16;
        {
            int r = t >> 1, h = t & 1;
            uint4 raw = *(const uint4*)&g_p[bbase + (size_t)(n0 + r) * NTOK + mbase + h * 8];
            unsigned uw[4] = {raw.x, raw.y, raw.z, raw.w};
            #pragma unroll
            for (int j = 0; j < 4; j++) {
                float flo = __uint_as_float(uw[j] << 16);
                float fhi = __uint_as_float(uw[j] & 0xffff0000u);
                sPd[r][h * 8 + j * 2 + 0] = pk(flo, flo);
                sPd[r][h * 8 + j * 2 + 1] = pk(fhi, fhi);
            }
        }
        {
            int r = t >> 4, c4 = t & 15;
            *(float4*)&sV[r][c4 * 4] = *(const float4*)&g_v[(((b << 12) + mbase + r) << 6) + c4 * 4];
        }
        __syncthreads();

        #pragma unroll 16
        for (int m = 0; m < 16; m++) {
            F4P bv;
            bv.f = *(float4*)&sV[m][tx * 4];
            #pragma unroll
            for (int i = 0; i < 8; i++) {
                u64 ap = sPd[ty * 8 + i][m];
                fma2(acc[i][0], ap, bv.p[0]);
                fma2(acc[i][1], ap, bv.p[1]);
            }
        }
        __syncthreads();
    }

    #pragma unroll
    for (int i = 0; i < 8; i++) {
        int nn = n0 + ty * 8 + i;
        #pragma unroll
        for (int j = 0; j < 2; j++) {
            float lo, hi;
            unpk(acc[i][j], lo, hi);
            int c0 = tx * 4 + j * 2;
            atomicAdd(&g_o[(size_t)(((b << 6) + c0) << 12) + nn], lo);
            atomicAdd(&g_o[(size_t)(((b << 6) + c0 + 1) << 12) + nn], hi);
        }
    }
}

// ---------------- kernel 5: output projection + bias + residual ----------------
__global__ __launch_bounds__(256) void proj_kernel(const float* __restrict__ x,
                                                   const float* __restrict__ w_out,
                                                   const float* __restrict__ b_out,
                                                   const float* __restrict__ gamma,
                                                   float* __restrict__ out)
{
    __shared__ float sT[64][64];
    const int b  = blockIdx.y;
    const int n0 = blockIdx.x * 64;
    const int t  = threadIdx.x;

    for (int idx = t; idx < 64 * 64; idx += 256) {
        int c = idx >> 6, j = idx & 63;
        sT[c][j] = g_o[(((b << 6) + c) << 12) + n0 + j];
    }
    __syncthreads();

    const float g = gamma[0];
    for (int r = 0; r < 16; r++) {
        int outIdx = t + (r << 8);
        int o = outIdx >> 6, j = outIdx & 63;
        const float* wrow = w_out + o * 64;
        float acc = b_out[o];
        #pragma unroll
        for (int c = 0; c < 64; c++) acc += wrow[c] * sT[c][j];
        size_t gi = (size_t)(((b << 6) + o) << 12) + n0 + j;
        out[gi] = g * acc + x[gi];
    }
}

// ---------------- launch ----------------
extern "C" void kernel_launch(void* const* d_in, const int* in_sizes, int n_in,
                              void* d_out, int out_size)
{
    const float* x     = (const float*)d_in[0];
    const float* skip  = (const float*)d_in[1];
    const float* w_qkv = (const float*)d_in[2];
    const float* w_out = (const float*)d_in[3];
    const float* b_out = (const float*)d_in[4];
    const float* gamma = (const float*)d_in[5];
    float* out = (float*)d_out;

    zero_o_kernel<<<1024, 256>>>();
    qkv_kernel<<<dim3(64, BATCH), 256>>>(x, skip, w_qkv);
    scores_kernel<<<dim3(32, 64, BATCH), 256>>>();
    select_softmax_kernel<<<BATCH * NTOK, 256>>>();
    av_kernel<<<dim3(32, 8, BATCH), 256>>>();
    proj_kernel<<<dim3(64, BATCH), 256>>>(x, w_out, b_out, gamma, out);
}

// round 8
// speedup vs baseline: 2.5592x; 2.0994x over previous
#include <cuda_runtime.h>
#include <cuda_bf16.h>
#include <cstdint>

#define BATCH 4
#define NTOK  4096
#define KSEL  1024

// ---------------- global scratch ----------------
__device__ __nv_bfloat16 g_q [BATCH * NTOK * 64];   // (b, n, c) bf16, pre-scaled
__device__ __nv_bfloat16 g_kT[BATCH * NTOK * 64];   // (b, m, c) bf16
__device__ __nv_bfloat16 g_v [BATCH * 64 * NTOK];   // (b, c, m) bf16
__device__ float         g_s [BATCH * NTOK * NTOK]; // (b, n, m) fp32 scores
__device__ __nv_bfloat16 g_p [BATCH * NTOK * NTOK]; // (b, n, m) bf16 probabilities
__device__ float         g_o [BATCH * NTOK * 64];   // (b, n, c) fp32

__device__ __forceinline__ uint32_t smem_u32(const void* p) {
    uint32_t a;
    asm("{ .reg .u64 t; cvta.to.shared.u64 t, %1; cvt.u32.u64 %0, t; }" : "=r"(a) : "l"(p));
    return a;
}
__device__ __forceinline__ unsigned pack_bf16x2(float hi, float lo) {
    unsigned r;
    asm("cvt.rn.bf16x2.f32 %0, %1, %2;" : "=r"(r) : "f"(hi), "f"(lo));
    return r;
}
// XOR swizzle of 16B chunks within a 128B row
#define SWZ(row, chunkByte) ((chunkByte) ^ (((row) & 7) << 4))

__device__ __forceinline__ void ldm_x4(uint32_t* a, uint32_t addr) {
    asm volatile("ldmatrix.sync.aligned.m8n8.x4.shared.b16 {%0,%1,%2,%3}, [%4];"
                 : "=r"(a[0]), "=r"(a[1]), "=r"(a[2]), "=r"(a[3]) : "r"(addr));
}
__device__ __forceinline__ void ldm_x2(uint32_t* b, uint32_t addr) {
    asm volatile("ldmatrix.sync.aligned.m8n8.x2.shared.b16 {%0,%1}, [%2];"
                 : "=r"(b[0]), "=r"(b[1]) : "r"(addr));
}
__device__ __forceinline__ void mma_bf16(float* c, const uint32_t* a, const uint32_t* b) {
    asm volatile("mma.sync.aligned.m16n8k16.row.col.f32.bf16.bf16.f32 "
                 "{%0,%1,%2,%3}, {%4,%5,%6,%7}, {%8,%9}, {%0,%1,%2,%3};"
                 : "+f"(c[0]), "+f"(c[1]), "+f"(c[2]), "+f"(c[3])
                 : "r"(a[0]), "r"(a[1]), "r"(a[2]), "r"(a[3]), "r"(b[0]), "r"(b[1]));
}

// ---------------- kernel 1: fused QKV projection (fp32 math -> bf16 stores) ----------------
__global__ __launch_bounds__(256) void qkv_kernel(const float* __restrict__ x,
                                                  const float* __restrict__ skip,
                                                  const float* __restrict__ w_qkv)
{
    __shared__ float sx[64][64];
    __shared__ float ss[64][64];
    const int b  = blockIdx.y;
    const int n0 = blockIdx.x * 64;
    const int t  = threadIdx.x;

    for (int idx = t; idx < 64 * 64; idx += 256) {
        int c = idx >> 6, j = idx & 63;
        sx[c][j] = x[((b * 64 + c) << 12) + n0 + j];
        ss[c][j] = skip[((b * 64 + c) << 12) + n0 + j];
    }
    __syncthreads();

    const float scale = 0.125f;
    for (int r = 0; r < 48; r++) {
        int outIdx = t + (r << 8);
        int sel = outIdx >> 12;
        int rem = outIdx & 4095;
        int o = rem >> 6, j = rem & 63;
        const float* wrow = w_qkv + ((sel << 6) + o) * 64;
        float acc = 0.f;
        if (sel == 0) {
            #pragma unroll
            for (int c = 0; c < 64; c++) acc += wrow[c] * sx[c][j];
            g_q[(size_t)(((b << 12) + n0 + j) << 6) + o] = __float2bfloat16(acc * scale);
        } else {
            #pragma unroll
            for (int c = 0; c < 64; c++) acc += wrow[c] * ss[c][j];
            if (sel == 1) g_kT[(size_t)(((b << 12) + n0 + j) << 6) + o] = __float2bfloat16(acc);
            else          g_v [(size_t)(((b << 6) + o) << 12) + n0 + j] = __float2bfloat16(acc);
        }
    }
}

// ---------------- kernel 2: S = Q K^T via mma.sync bf16, 128n x 128m per CTA ----------------
__global__ __launch_bounds__(256) void scores_mma()
{
    __shared__ __align__(16) char sQ[128 * 128];   // [n row][64 bf16 = 128B], swizzled
    __shared__ __align__(16) char sK[128 * 128];   // [m row][64 bf16], swizzled
    const int b = blockIdx.z, n0 = blockIdx.y * 128, m0 = blockIdx.x * 128;
    const int t = threadIdx.x, wid = t >> 5, lane = t & 31;
    const uint32_t sQb = smem_u32(sQ), sKb = smem_u32(sK);

    #pragma unroll
    for (int k = 0; k < 4; k++) {
        int i = t + k * 256;
        int r = i >> 3, q = i & 7;
        *(uint4*)(sQ + r * 128 + SWZ(r, q * 16)) =
            *(const uint4*)&g_q[(size_t)((b << 12) + n0 + r) * 64 + q * 8];
        *(uint4*)(sK + r * 128 + SWZ(r, q * 16)) =
            *(const uint4*)&g_kT[(size_t)((b << 12) + m0 + r) * 64 + q * 8];
    }
    __syncthreads();

    const int wn = wid >> 2, wm = wid & 3;   // warp tile: 64n x 32m
    float acc[4][4][4];
    #pragma unroll
    for (int i = 0; i < 4; i++)
        #pragma unroll
        for (int j = 0; j < 4; j++)
            #pragma unroll
            for (int e = 0; e < 4; e++) acc[i][j][e] = 0.f;

    #pragma unroll
    for (int ki = 0; ki < 4; ki++) {
        uint32_t afr[4][4], bfr[4][2];
        #pragma unroll
        for (int i = 0; i < 4; i++) {
            int row = wn * 64 + i * 16 + (lane & 15);
            int cb = ki * 32 + (lane >> 4) * 16;
            ldm_x4(afr[i], sQb + row * 128 + SWZ(row, cb));
        }
        #pragma unroll
        for (int j = 0; j < 4; j++) {
            int row = wm * 32 + j * 8 + (lane & 7);
            int cb = ki * 32 + ((lane >> 3) & 1) * 16;
            ldm_x2(bfr[j], sKb + row * 128 + SWZ(row, cb));
        }
        #pragma unroll
        for (int i = 0; i < 4; i++)
            #pragma unroll
            for (int j = 0; j < 4; j++)
                mma_bf16(acc[i][j], afr[i], bfr[j]);
    }

    const int gid = lane >> 2, tc = lane & 3;
    #pragma unroll
    for (int i = 0; i < 4; i++) {
        int row = n0 + wn * 64 + i * 16 + gid;
        size_t r0 = ((size_t)b << 24) + (size_t)row * NTOK + m0 + wm * 32;
        size_t r1 = r0 + 8 * NTOK;
        #pragma unroll
        for (int j = 0; j < 4; j++) {
            *(float2*)&g_s[r0 + j * 8 + tc * 2] = make_float2(acc[i][j][0], acc[i][j][1]);
            *(float2*)&g_s[r1 + j * 8 + tc * 2] = make_float2(acc[i][j][2], acc[i][j][3]);
        }
    }
}

// ---------------- kernel 3: value-histogram top-k threshold + masked softmax -> bf16 ----------------
__global__ __launch_bounds__(256) void select_softmax_kernel()
{
    const int row = blockIdx.x;
    const int b = row >> 12, n = row & 4095;
    const size_t base = ((size_t)b << 24) + (size_t)n * NTOK;
    const int t = threadIdx.x;
    const int wid = t >> 5, lane = t & 31;

    __shared__ int hist8[8][256];
    __shared__ float candF[4096];
    __shared__ float warpMax[8], warpMin[8];
    __shared__ int warpTot[8];
    __shared__ int sh_cnt;
    __shared__ int sh_bin, sh_kk;
    __shared__ float sh_thr, sh_z;

    if (t == 0) { sh_cnt = 0; sh_z = 0.f; }
    #pragma unroll
    for (int w = 0; w < 8; w++) hist8[w][t] = 0;

    float vals[16];
    const size_t myb = base + (size_t)t * 16;
    #pragma unroll
    for (int k = 0; k < 4; k++) {
        float4 f = *(const float4*)&g_s[myb + k * 4];
        vals[k * 4 + 0] = f.x; vals[k * 4 + 1] = f.y;
        vals[k * 4 + 2] = f.z; vals[k * 4 + 3] = f.w;
    }

    float mymax = vals[0], mymin = vals[0];
    #pragma unroll
    for (int i = 1; i < 16; i++) {
        mymax = fmaxf(mymax, vals[i]);
        mymin = fminf(mymin, vals[i]);
    }
    #pragma unroll
    for (int off = 16; off; off >>= 1) {
        mymax = fmaxf(mymax, __shfl_xor_sync(0xffffffffu, mymax, off));
        mymin = fminf(mymin, __shfl_xor_sync(0xffffffffu, mymin, off));
    }
    if (lane == 0) { warpMax[wid] = mymax; warpMin[wid] = mymin; }
    __syncthreads();
    float rmax = warpMax[0], rmin = warpMin[0];
    #pragma unroll
    for (int w = 1; w < 8; w++) {
        rmax = fmaxf(rmax, warpMax[w]);
        rmin = fminf(rmin, warpMin[w]);
    }

    float range = rmax - rmin;
    float scale = 256.0f / (range + 1e-30f) * (1.0f - 1e-6f);
    int* myh = hist8[wid];
    int bins[16];
    #pragma unroll
    for (int i = 0; i < 16; i++) {
        int bin = (int)((vals[i] - rmin) * scale);
        bin = bin < 0 ? 0 : (bin > 255 ? 255 : bin);
        bins[i] = bin;
        atomicAdd(&myh[bin], 1);
    }
    __syncthreads();

    int tot = 0;
    #pragma unroll
    for (int w = 0; w < 8; w++) tot += hist8[w][t];
    int v = tot;
    #pragma unroll
    for (int off = 1; off < 32; off <<= 1) {
        int o = __shfl_down_sync(0xffffffffu, v, off);
        if (lane + off < 32) v += o;
    }
    if (lane == 0) warpTot[wid] = v;
    __syncthreads();
    int above = 0;
    #pragma unroll
    for (int w = 0; w < 8; w++) if (w > wid) above += warpTot[w];
    int cum_incl = v + above, cum_excl = cum_incl - tot;
    if (cum_excl < KSEL && KSEL <= cum_incl) { sh_bin = t; sh_kk = KSEL - cum_excl; }
    __syncthreads();
    const int selbin = sh_bin;
    const int kk = sh_kk;

    {
        int cnt = 0;
        #pragma unroll
        for (int i = 0; i < 16; i++) cnt += (bins[i] == selbin);
        int pos = 0;
        if (cnt) pos = atomicAdd(&sh_cnt, cnt);
        #pragma unroll
        for (int i = 0; i < 16; i++)
            if (bins[i] == selbin) candF[pos++] = vals[i];
    }
    __syncthreads();
    const int ncand = sh_cnt;

    for (int i = t; i < ncand; i += 256) {
        float xx = candF[i];
        int gt = 0, eq = 0;
        for (int j = 0; j < ncand; j++) {
            float y = candF[j];
            gt += (y > xx);
            eq += (y == xx);
        }
        if (gt < kk && kk <= gt + eq) sh_thr = xx;
    }
    __syncthreads();

    const float thr = sh_thr;
    const float M = fmaxf(rmax, 0.f);
    const float expM = __expf(-M);

    float w[16];
    float zloc = 0.f;
    #pragma unroll
    for (int i = 0; i < 16; i++) {
        float wv = (vals[i] >= thr) ? __expf(vals[i] - M) : expM;
        w[i] = wv;
        zloc += wv;
    }
    #pragma unroll
    for (int off = 16; off; off >>= 1) zloc += __shfl_xor_sync(0xffffffffu, zloc, off);
    if (lane == 0) atomicAdd(&sh_z, zloc);
    __syncthreads();

    float invZ = 1.f / sh_z;
    #pragma unroll
    for (int h = 0; h < 2; h++) {
        uint4 o;
        o.x = pack_bf16x2(w[h*8+1] * invZ, w[h*8+0] * invZ);
        o.y = pack_bf16x2(w[h*8+3] * invZ, w[h*8+2] * invZ);
        o.z = pack_bf16x2(w[h*8+5] * invZ, w[h*8+4] * invZ);
        o.w = pack_bf16x2(w[h*8+7] * invZ, w[h*8+6] * invZ);
        *(uint4*)&g_p[myb + h * 8] = o;
    }
}

// ---------------- kernel 4: O(n,c) = P V^T via mma.sync bf16, 64n x 64c per CTA ----------------
__global__ __launch_bounds__(256) void av_mma()
{
    __shared__ __align__(16) char sP[64 * 128];   // [n row][64 m bf16], swizzled
    __shared__ __align__(16) char sV[64 * 128];   // [c row][64 m bf16], swizzled
    const int b = blockIdx.y, n0 = blockIdx.x * 64;
    const int t = threadIdx.x, wid = t >> 5, lane = t & 31;
    const uint32_t sPb = smem_u32(sP), sVb = smem_u32(sV);
    const size_t pb = ((size_t)b << 24);

    const int wn = wid >> 2, wc = wid & 3;   // warp tile: 32n x 16c
    float acc[2][2][4];
    #pragma unroll
    for (int i = 0; i < 2; i++)
        #pragma unroll
        for (int j = 0; j < 2; j++)
            #pragma unroll
            for (int e = 0; e < 4; e++) acc[i][j][e] = 0.f;

    for (int mt = 0; mt < 64; mt++) {
        const int mbase = mt * 64;
        #pragma unroll
        for (int k = 0; k < 2; k++) {
            int i = t + k * 256;
            int r = i >> 3, q = i & 7;
            *(uint4*)(sP + r * 128 + SWZ(r, q * 16)) =
                *(const uint4*)&g_p[pb + (size_t)(n0 + r) * NTOK + mbase + q * 8];
            *(uint4*)(sV + r * 128 + SWZ(r, q * 16)) =
                *(const uint4*)&g_v[(size_t)(((b << 6) + r) << 12) + mbase + q * 8];
        }
        __syncthreads();

        #pragma unroll
        for (int ki = 0; ki < 4; ki++) {
            uint32_t afr[2][4], bfr[2][2];
            #pragma unroll
            for (int i = 0; i < 2; i++) {
                int row = wn * 32 + i * 16 + (lane & 15);
                int cb = ki * 32 + (lane >> 4) * 16;
                ldm_x4(afr[i], sPb + row * 128 + SWZ(row, cb));
            }
            #pragma unroll
            for (int j = 0; j < 2; j++) {
                int row = wc * 16 + j * 8 + (lane & 7);
                int cb = ki * 32 + ((lane >> 3) & 1) * 16;
                ldm_x2(bfr[j], sVb + row * 128 + SWZ(row, cb));
            }
            #pragma unroll
            for (int i = 0; i < 2; i++)
                #pragma unroll
                for (int j = 0; j < 2; j++)
                    mma_bf16(acc[i][j], afr[i], bfr[j]);
        }
        __syncthreads();
    }

    const int gid = lane >> 2, tc = lane & 3;
    #pragma unroll
    for (int i = 0; i < 2; i++) {
        int row = n0 + wn * 32 + i * 16 + gid;
        size_t r0 = (size_t)((b << 12) + row) * 64 + wc * 16;
        size_t r1 = r0 + 8 * 64;
        #pragma unroll
        for (int j = 0; j < 2; j++) {
            *(float2*)&g_o[r0 + j * 8 + tc * 2] = make_float2(acc[i][j][0], acc[i][j][1]);
            *(float2*)&g_o[r1 + j * 8 + tc * 2] = make_float2(acc[i][j][2], acc[i][j][3]);
        }
    }
}

// ---------------- kernel 5: output projection + bias + residual ----------------
__global__ __launch_bounds__(256) void proj_kernel(const float* __restrict__ x,
                                                   const float* __restrict__ w_out,
                                                   const float* __restrict__ b_out,
                                                   const float* __restrict__ gamma,
                                                   float* __restrict__ out)
{
    __shared__ float sT[64][65];
    const int b  = blockIdx.y;
    const int n0 = blockIdx.x * 64;
    const int t  = threadIdx.x;

    // g_o is (b, n, c): transpose into sT[c][j]
    for (int idx = t; idx < 64 * 64; idx += 256) {
        int j = idx >> 6, c = idx & 63;
        sT[c][j] = g_o[(size_t)((b << 12) + n0 + j) * 64 + c];
    }
    __syncthreads();

    const float g = gamma[0];
    for (int r = 0; r < 16; r++) {
        int outIdx = t + (r << 8);
        int o = outIdx >> 6, j = outIdx & 63;
        const float* wrow = w_out + o * 64;
        float acc = b_out[o];
        #pragma unroll
        for (int c = 0; c < 64; c++) acc += wrow[c] * sT[c][j];
        size_t gi = (size_t)(((b << 6) + o) << 12) + n0 + j;
        out[gi] = g * acc + x[gi];
    }
}

// ---------------- launch ----------------
extern "C" void kernel_launch(void* const* d_in, const int* in_sizes, int n_in,
                              void* d_out, int out_size)
{
    const float* x     = (const float*)d_in[0];
    const float* skip  = (const float*)d_in[1];
    const float* w_qkv = (const float*)d_in[2];
    const float* w_out = (const float*)d_in[3];
    const float* b_out = (const float*)d_in[4];
    const float* gamma = (const float*)d_in[5];
    float* out = (float*)d_out;

    qkv_kernel<<<dim3(64, BATCH), 256>>>(x, skip, w_qkv);
    scores_mma<<<dim3(32, 32, BATCH), 256>>>();
    select_softmax_kernel<<<BATCH * NTOK, 256>>>();
    av_mma<<<dim3(64, BATCH), 256>>>();
    proj_kernel<<<dim3(64, BATCH), 256>>>(x, w_out, b_out, gamma, out);
}

// round 9
// speedup vs baseline: 2.8596x; 1.1174x over previous
#include <cuda_runtime.h>
#include <cuda_bf16.h>
#include <cstdint>

#define BATCH 4
#define NTOK  4096
#define KSEL  1024

// ---------------- global scratch ----------------
__device__ __nv_bfloat16 g_q [BATCH * NTOK * 64];   // (b, n, c) bf16, pre-scaled
__device__ __nv_bfloat16 g_kT[BATCH * NTOK * 64];   // (b, m, c) bf16
__device__ __nv_bfloat16 g_v [BATCH * 64 * NTOK];   // (b, c, m) bf16
__device__ float         g_s [BATCH * NTOK * NTOK]; // (b, n, m) fp32 scores
__device__ __nv_bfloat16 g_p [BATCH * NTOK * NTOK]; // (b, n, m) bf16 probabilities
__device__ float         g_o [BATCH * NTOK * 64];   // (b, n, c) fp32

__device__ __forceinline__ uint32_t smem_u32(const void* p) {
    uint32_t a;
    asm("{ .reg .u64 t; cvta.to.shared.u64 t, %1; cvt.u32.u64 %0, t; }" : "=r"(a) : "l"(p));
    return a;
}
__device__ __forceinline__ unsigned pack_bf16x2(float hi, float lo) {
    unsigned r;
    asm("cvt.rn.bf16x2.f32 %0, %1, %2;" : "=r"(r) : "f"(hi), "f"(lo));
    return r;
}
#define SWZ(row, chunkByte) ((chunkByte) ^ (((row) & 7) << 4))

__device__ __forceinline__ void cp16(uint32_t saddr, const void* gaddr) {
    asm volatile("cp.async.cg.shared.global [%0], [%1], 16;" :: "r"(saddr), "l"(gaddr));
}
#define CP_COMMIT() asm volatile("cp.async.commit_group;" ::: "memory")
#define CP_WAIT(n)  asm volatile("cp.async.wait_group %0;" :: "n"(n) : "memory")

__device__ __forceinline__ void ldm_x4(uint32_t* a, uint32_t addr) {
    asm volatile("ldmatrix.sync.aligned.m8n8.x4.shared.b16 {%0,%1,%2,%3}, [%4];"
                 : "=r"(a[0]), "=r"(a[1]), "=r"(a[2]), "=r"(a[3]) : "r"(addr));
}
__device__ __forceinline__ void ldm_x2(uint32_t* b, uint32_t addr) {
    asm volatile("ldmatrix.sync.aligned.m8n8.x2.shared.b16 {%0,%1}, [%2];"
                 : "=r"(b[0]), "=r"(b[1]) : "r"(addr));
}
__device__ __forceinline__ void mma_bf16(float* c, const uint32_t* a, const uint32_t* b) {
    asm volatile("mma.sync.aligned.m16n8k16.row.col.f32.bf16.bf16.f32 "
                 "{%0,%1,%2,%3}, {%4,%5,%6,%7}, {%8,%9}, {%0,%1,%2,%3};"
                 : "+f"(c[0]), "+f"(c[1]), "+f"(c[2]), "+f"(c[3])
                 : "r"(a[0]), "r"(a[1]), "r"(a[2]), "r"(a[3]), "r"(b[0]), "r"(b[1]));
}

// ---------------- kernel 1: fused QKV projection ----------------
__global__ __launch_bounds__(256) void qkv_kernel(const float* __restrict__ x,
                                                  const float* __restrict__ skip,
                                                  const float* __restrict__ w_qkv)
{
    __shared__ float sx[64][64];
    __shared__ float ss[64][64];
    const int b  = blockIdx.y;
    const int n0 = blockIdx.x * 64;
    const int t  = threadIdx.x;

    for (int idx = t; idx < 64 * 64; idx += 256) {
        int c = idx >> 6, j = idx & 63;
        sx[c][j] = x[((b * 64 + c) << 12) + n0 + j];
        ss[c][j] = skip[((b * 64 + c) << 12) + n0 + j];
    }
    __syncthreads();

    const float scale = 0.125f;
    for (int r = 0; r < 48; r++) {
        int outIdx = t + (r << 8);
        int sel = outIdx >> 12;
        int rem = outIdx & 4095;
        int o = rem >> 6, j = rem & 63;
        const float* wrow = w_qkv + ((sel << 6) + o) * 64;
        float acc = 0.f;
        if (sel == 0) {
            #pragma unroll
            for (int c = 0; c < 64; c++) acc += wrow[c] * sx[c][j];
            g_q[(size_t)(((b << 12) + n0 + j) << 6) + o] = __float2bfloat16(acc * scale);
        } else {
            #pragma unroll
            for (int c = 0; c < 64; c++) acc += wrow[c] * ss[c][j];
            if (sel == 1) g_kT[(size_t)(((b << 12) + n0 + j) << 6) + o] = __float2bfloat16(acc);
            else          g_v [(size_t)(((b << 6) + o) << 12) + n0 + j] = __float2bfloat16(acc);
        }
    }
}

// ---------------- kernel 2: S = Q K^T, 128n x 512m per CTA, cp.async 2-stage on K ----------------
__global__ __launch_bounds__(256) void scores_mma()
{
    __shared__ __align__(16) char sQ[128 * 128];       // 16 KB
    __shared__ __align__(16) char sK[2][128 * 128];    // 32 KB
    const int b = blockIdx.z, n0 = blockIdx.y * 128, mB = blockIdx.x * 512;
    const int t = threadIdx.x, wid = t >> 5, lane = t & 31;
    const uint32_t sQb = smem_u32(sQ);
    const uint32_t sKb0 = smem_u32(sK[0]);

    // group 0: Q + K tile 0
    #pragma unroll
    for (int k = 0; k < 4; k++) {
        int i = t + k * 256;
        int r = i >> 3, q = i & 7;
        cp16(sQb + r * 128 + SWZ(r, q * 16),
             &g_q[(size_t)((b << 12) + n0 + r) * 64 + q * 8]);
        cp16(sKb0 + r * 128 + SWZ(r, q * 16),
             &g_kT[(size_t)((b << 12) + mB + r) * 64 + q * 8]);
    }
    CP_COMMIT();

    const int wn = wid >> 2, wm = wid & 3;   // warp tile: 64n x 32m
    const int gid = lane >> 2, tc = lane & 3;

    for (int mi = 0; mi < 4; mi++) {
        const uint32_t sKc = sKb0 + (mi & 1) * 16384;
        if (mi < 3) {
            const uint32_t sKn = sKb0 + ((mi + 1) & 1) * 16384;
            const int m0n = mB + (mi + 1) * 128;
            #pragma unroll
            for (int k = 0; k < 4; k++) {
                int i = t + k * 256;
                int r = i >> 3, q = i & 7;
                cp16(sKn + r * 128 + SWZ(r, q * 16),
                     &g_kT[(size_t)((b << 12) + m0n + r) * 64 + q * 8]);
            }
            CP_COMMIT();
            CP_WAIT(1);
        } else {
            CP_WAIT(0);
        }
        __syncthreads();

        float acc[4][4][4];
        #pragma unroll
        for (int i = 0; i < 4; i++)
            #pragma unroll
            for (int j = 0; j < 4; j++)
                #pragma unroll
                for (int e = 0; e < 4; e++) acc[i][j][e] = 0.f;

        #pragma unroll
        for (int ki = 0; ki < 4; ki++) {
            uint32_t afr[4][4], bfr[4][2];
            #pragma unroll
            for (int i = 0; i < 4; i++) {
                int row = wn * 64 + i * 16 + (lane & 15);
                int cb = ki * 32 + (lane >> 4) * 16;
                ldm_x4(afr[i], sQb + row * 128 + SWZ(row, cb));
            }
            #pragma unroll
            for (int j = 0; j < 4; j++) {
                int row = wm * 32 + j * 8 + (lane & 7);
                int cb = ki * 32 + ((lane >> 3) & 1) * 16;
                ldm_x2(bfr[j], sKc + row * 128 + SWZ(row, cb));
            }
            #pragma unroll
            for (int i = 0; i < 4; i++)
                #pragma unroll
                for (int j = 0; j < 4; j++)
                    mma_bf16(acc[i][j], afr[i], bfr[j]);
        }

        const int m0 = mB + mi * 128;
        #pragma unroll
        for (int i = 0; i < 4; i++) {
            int row = n0 + wn * 64 + i * 16 + gid;
            size_t r0 = ((size_t)b << 24) + (size_t)row * NTOK + m0 + wm * 32;
            size_t r1 = r0 + 8 * NTOK;
            #pragma unroll
            for (int j = 0; j < 4; j++) {
                *(float2*)&g_s[r0 + j * 8 + tc * 2] = make_float2(acc[i][j][0], acc[i][j][1]);
                *(float2*)&g_s[r1 + j * 8 + tc * 2] = make_float2(acc[i][j][2], acc[i][j][3]);
            }
        }
        __syncthreads();
    }
}

// ---------------- kernel 3: value-histogram top-k threshold + masked softmax -> bf16 ----------------
__global__ __launch_bounds__(256) void select_softmax_kernel()
{
    const int row = blockIdx.x;
    const int b = row >> 12, n = row & 4095;
    const size_t base = ((size_t)b << 24) + (size_t)n * NTOK;
    const int t = threadIdx.x;
    const int wid = t >> 5, lane = t & 31;

    __shared__ int hist8[8][256];
    __shared__ float candF[4096];
    __shared__ float warpMax[8], warpMin[8];
    __shared__ int warpTot[8];
    __shared__ int sh_cnt;
    __shared__ int sh_bin, sh_kk;
    __shared__ float sh_thr, sh_z;

    if (t == 0) { sh_cnt = 0; sh_z = 0.f; }
    #pragma unroll
    for (int w = 0; w < 8; w++) hist8[w][t] = 0;

    float vals[16];
    const size_t myb = base + (size_t)t * 16;
    #pragma unroll
    for (int k = 0; k < 4; k++) {
        float4 f = *(const float4*)&g_s[myb + k * 4];
        vals[k * 4 + 0] = f.x; vals[k * 4 + 1] = f.y;
        vals[k * 4 + 2] = f.z; vals[k * 4 + 3] = f.w;
    }

    float mymax = vals[0], mymin = vals[0];
    #pragma unroll
    for (int i = 1; i < 16; i++) {
        mymax = fmaxf(mymax, vals[i]);
        mymin = fminf(mymin, vals[i]);
    }
    #pragma unroll
    for (int off = 16; off; off >>= 1) {
        mymax = fmaxf(mymax, __shfl_xor_sync(0xffffffffu, mymax, off));
        mymin = fminf(mymin, __shfl_xor_sync(0xffffffffu, mymin, off));
    }
    if (lane == 0) { warpMax[wid] = mymax; warpMin[wid] = mymin; }
    __syncthreads();
    float rmax = warpMax[0], rmin = warpMin[0];
    #pragma unroll
    for (int w = 1; w < 8; w++) {
        rmax = fmaxf(rmax, warpMax[w]);
        rmin = fminf(rmin, warpMin[w]);
    }

    float range = rmax - rmin;
    float scale = 256.0f / (range + 1e-30f) * (1.0f - 1e-6f);
    int* myh = hist8[wid];
    int bins[16];
    #pragma unroll
    for (int i = 0; i < 16; i++) {
        int bin = (int)((vals[i] - rmin) * scale);
        bin = bin < 0 ? 0 : (bin > 255 ? 255 : bin);
        bins[i] = bin;
        atomicAdd(&myh[bin], 1);
    }
    __syncthreads();

    int tot = 0;
    #pragma unroll
    for (int w = 0; w < 8; w++) tot += hist8[w][t];
    int v = tot;
    #pragma unroll
    for (int off = 1; off < 32; off <<= 1) {
        int o = __shfl_down_sync(0xffffffffu, v, off);
        if (lane + off < 32) v += o;
    }
    if (lane == 0) warpTot[wid] = v;
    __syncthreads();
    int above = 0;
    #pragma unroll
    for (int w = 0; w < 8; w++) if (w > wid) above += warpTot[w];
    int cum_incl = v + above, cum_excl = cum_incl - tot;
    if (cum_excl < KSEL && KSEL <= cum_incl) { sh_bin = t; sh_kk = KSEL - cum_excl; }
    __syncthreads();
    const int selbin = sh_bin;
    const int kk = sh_kk;

    {
        int cnt = 0;
        #pragma unroll
        for (int i = 0; i < 16; i++) cnt += (bins[i] == selbin);
        int pos = 0;
        if (cnt) pos = atomicAdd(&sh_cnt, cnt);
        #pragma unroll
        for (int i = 0; i < 16; i++)
            if (bins[i] == selbin) candF[pos++] = vals[i];
    }
    __syncthreads();
    const int ncand = sh_cnt;

    for (int i = t; i < ncand; i += 256) {
        float xx = candF[i];
        int gt = 0, eq = 0;
        for (int j = 0; j < ncand; j++) {
            float y = candF[j];
            gt += (y > xx);
            eq += (y == xx);
        }
        if (gt < kk && kk <= gt + eq) sh_thr = xx;
    }
    __syncthreads();

    const float thr = sh_thr;
    const float M = fmaxf(rmax, 0.f);
    const float expM = __expf(-M);

    float w[16];
    float zloc = 0.f;
    #pragma unroll
    for (int i = 0; i < 16; i++) {
        float wv = (vals[i] >= thr) ? __expf(vals[i] - M) : expM;
        w[i] = wv;
        zloc += wv;
    }
    #pragma unroll
    for (int off = 16; off; off >>= 1) zloc += __shfl_xor_sync(0xffffffffu, zloc, off);
    if (lane == 0) atomicAdd(&sh_z, zloc);
    __syncthreads();

    float invZ = 1.f / sh_z;
    #pragma unroll
    for (int h = 0; h < 2; h++) {
        uint4 o;
        o.x = pack_bf16x2(w[h*8+1] * invZ, w[h*8+0] * invZ);
        o.y = pack_bf16x2(w[h*8+3] * invZ, w[h*8+2] * invZ);
        o.z = pack_bf16x2(w[h*8+5] * invZ, w[h*8+4] * invZ);
        o.w = pack_bf16x2(w[h*8+7] * invZ, w[h*8+6] * invZ);
        *(uint4*)&g_p[myb + h * 8] = o;
    }
}

// ---------------- kernel 4: O(n,c) = P V^T, 64n x 64c per CTA, cp.async 2-stage ----------------
__global__ __launch_bounds__(256) void av_mma()
{
    __shared__ __align__(16) char sP[2][64 * 128];   // 16 KB
    __shared__ __align__(16) char sV[2][64 * 128];   // 16 KB
    const int b = blockIdx.y, n0 = blockIdx.x * 64;
    const int t = threadIdx.x, wid = t >> 5, lane = t & 31;
    const uint32_t sPb0 = smem_u32(sP[0]), sVb0 = smem_u32(sV[0]);
    const size_t pb = ((size_t)b << 24);

    // preload chunk 0
    #pragma unroll
    for (int k = 0; k < 2; k++) {
        int i = t + k * 256;
        int r = i >> 3, q = i & 7;
        cp16(sPb0 + r * 128 + SWZ(r, q * 16),
             &g_p[pb + (size_t)(n0 + r) * NTOK + q * 8]);
        cp16(sVb0 + r * 128 + SWZ(r, q * 16),
             &g_v[(size_t)(((b << 6) + r) << 12) + q * 8]);
    }
    CP_COMMIT();

    const int wn = wid >> 2, wc = wid & 3;   // warp tile: 32n x 16c
    float acc[2][2][4];
    #pragma unroll
    for (int i = 0; i < 2; i++)
        #pragma unroll
        for (int j = 0; j < 2; j++)
            #pragma unroll
            for (int e = 0; e < 4; e++) acc[i][j][e] = 0.f;

    for (int mt = 0; mt < 64; mt++) {
        if (mt < 63) {
            const int mb = (mt + 1) * 64;
            const uint32_t sPn = sPb0 + ((mt + 1) & 1) * 8192;
            const uint32_t sVn = sVb0 + ((mt + 1) & 1) * 8192;
            #pragma unroll
            for (int k = 0; k < 2; k++) {
                int i = t + k * 256;
                int r = i >> 3, q = i & 7;
                cp16(sPn + r * 128 + SWZ(r, q * 16),
                     &g_p[pb + (size_t)(n0 + r) * NTOK + mb + q * 8]);
                cp16(sVn + r * 128 + SWZ(r, q * 16),
                     &g_v[(size_t)(((b << 6) + r) << 12) + mb + q * 8]);
            }
            CP_COMMIT();
            CP_WAIT(1);
        } else {
            CP_WAIT(0);
        }
        __syncthreads();

        const uint32_t sPc = sPb0 + (mt & 1) * 8192;
        const uint32_t sVc = sVb0 + (mt & 1) * 8192;
        #pragma unroll
        for (int ki = 0; ki < 4; ki++) {
            uint32_t afr[2][4], bfr[2][2];
            #pragma unroll
            for (int i = 0; i < 2; i++) {
                int row = wn * 32 + i * 16 + (lane & 15);
                int cb = ki * 32 + (lane >> 4) * 16;
                ldm_x4(afr[i], sPc + row * 128 + SWZ(row, cb));
            }
            #pragma unroll
            for (int j = 0; j < 2; j++) {
                int row = wc * 16 + j * 8 + (lane & 7);
                int cb = ki * 32 + ((lane >> 3) & 1) * 16;
                ldm_x2(bfr[j], sVc + row * 128 + SWZ(row, cb));
            }
            #pragma unroll
            for (int i = 0; i < 2; i++)
                #pragma unroll
                for (int j = 0; j < 2; j++)
                    mma_bf16(acc[i][j], afr[i], bfr[j]);
        }
        __syncthreads();
    }

    const int gid = lane >> 2, tc = lane & 3;
    #pragma unroll
    for (int i = 0; i < 2; i++) {
        int row = n0 + wn * 32 + i * 16 + gid;
        size_t r0 = (size_t)((b << 12) + row) * 64 + wc * 16;
        size_t r1 = r0 + 8 * 64;
        #pragma unroll
        for (int j = 0; j < 2; j++) {
            *(float2*)&g_o[r0 + j * 8 + tc * 2] = make_float2(acc[i][j][0], acc[i][j][1]);
            *(float2*)&g_o[r1 + j * 8 + tc * 2] = make_float2(acc[i][j][2], acc[i][j][3]);
        }
    }
}

// ---------------- kernel 5: output projection + bias + residual ----------------
__global__ __launch_bounds__(256) void proj_kernel(const float* __restrict__ x,
                                                   const float* __restrict__ w_out,
                                                   const float* __restrict__ b_out,
                                                   const float* __restrict__ gamma,
                                                   float* __restrict__ out)
{
    __shared__ float sT[64][65];
    const int b  = blockIdx.y;
    const int n0 = blockIdx.x * 64;
    const int t  = threadIdx.x;

    for (int idx = t; idx < 64 * 64; idx += 256) {
        int j = idx >> 6, c = idx & 63;
        sT[c][j] = g_o[(size_t)((b << 12) + n0 + j) * 64 + c];
    }
    __syncthreads();

    const float g = gamma[0];
    for (int r = 0; r < 16; r++) {
        int outIdx = t + (r << 8);
        int o = outIdx >> 6, j = outIdx & 63;
        const float* wrow = w_out + o * 64;
        float acc = b_out[o];
        #pragma unroll
        for (int c = 0; c < 64; c++) acc += wrow[c] * sT[c][j];
        size_t gi = (size_t)(((b << 6) + o) << 12) + n0 + j;
        out[gi] = g * acc + x[gi];
    }
}

// ---------------- launch ----------------
extern "C" void kernel_launch(void* const* d_in, const int* in_sizes, int n_in,
                              void* d_out, int out_size)
{
    const float* x     = (const float*)d_in[0];
    const float* skip  = (const float*)d_in[1];
    const float* w_qkv = (const float*)d_in[2];
    const float* w_out = (const float*)d_in[3];
    const float* b_out = (const float*)d_in[4];
    const float* gamma = (const float*)d_in[5];
    float* out = (float*)d_out;

    qkv_kernel<<<dim3(64, BATCH), 256>>>(x, skip, w_qkv);
    scores_mma<<<dim3(8, 32, BATCH), 256>>>();
    select_softmax_kernel<<<BATCH * NTOK, 256>>>();
    av_mma<<<dim3(64, BATCH), 256>>>();
    proj_kernel<<<dim3(64, BATCH), 256>>>(x, w_out, b_out, gamma, out);
}

// round 10
// speedup vs baseline: 2.9839x; 1.0435x over previous
#include <cuda_runtime.h>
#include <cuda_bf16.h>
#include <cstdint>

#define BATCH 4
#define NTOK  4096
#define KSEL  1024

// ---------------- global scratch ----------------
__device__ __nv_bfloat16 g_q [BATCH * NTOK * 64];   // (b, n, c) bf16, pre-scaled
__device__ __nv_bfloat16 g_kT[BATCH * NTOK * 64];   // (b, m, c) bf16
__device__ __nv_bfloat16 g_v [BATCH * 64 * NTOK];   // (b, c, m) bf16
__device__ __nv_bfloat16 g_sb[BATCH * NTOK * NTOK]; // (b, n, m) bf16 scores
__device__ __nv_bfloat16 g_p [BATCH * NTOK * NTOK]; // (b, n, m) bf16 probabilities
__device__ float         g_o [BATCH * NTOK * 64];   // (b, n, c) fp32

__device__ __forceinline__ uint32_t smem_u32(const void* p) {
    uint32_t a;
    asm("{ .reg .u64 t; cvta.to.shared.u64 t, %1; cvt.u32.u64 %0, t; }" : "=r"(a) : "l"(p));
    return a;
}
__device__ __forceinline__ unsigned pack_bf16x2(float hi, float lo) {
    unsigned r;
    asm("cvt.rn.bf16x2.f32 %0, %1, %2;" : "=r"(r) : "f"(hi), "f"(lo));
    return r;
}
#define SWZ(row, chunkByte) ((chunkByte) ^ (((row) & 7) << 4))

__device__ __forceinline__ void cp16(uint32_t saddr, const void* gaddr) {
    asm volatile("cp.async.cg.shared.global [%0], [%1], 16;" :: "r"(saddr), "l"(gaddr));
}
#define CP_COMMIT() asm volatile("cp.async.commit_group;" ::: "memory")
#define CP_WAIT(n)  asm volatile("cp.async.wait_group %0;" :: "n"(n) : "memory")

__device__ __forceinline__ void ldm_x4(uint32_t* a, uint32_t addr) {
    asm volatile("ldmatrix.sync.aligned.m8n8.x4.shared.b16 {%0,%1,%2,%3}, [%4];"
                 : "=r"(a[0]), "=r"(a[1]), "=r"(a[2]), "=r"(a[3]) : "r"(addr));
}
__device__ __forceinline__ void ldm_x2(uint32_t* b, uint32_t addr) {
    asm volatile("ldmatrix.sync.aligned.m8n8.x2.shared.b16 {%0,%1}, [%2];"
                 : "=r"(b[0]), "=r"(b[1]) : "r"(addr));
}
__device__ __forceinline__ void mma_bf16(float* c, const uint32_t* a, const uint32_t* b) {
    asm volatile("mma.sync.aligned.m16n8k16.row.col.f32.bf16.bf16.f32 "
                 "{%0,%1,%2,%3}, {%4,%5,%6,%7}, {%8,%9}, {%0,%1,%2,%3};"
                 : "+f"(c[0]), "+f"(c[1]), "+f"(c[2]), "+f"(c[3])
                 : "r"(a[0]), "r"(a[1]), "r"(a[2]), "r"(a[3]), "r"(b[0]), "r"(b[1]));
}

// ---------------- kernel 1: fused QKV projection ----------------
__global__ __launch_bounds__(256) void qkv_kernel(const float* __restrict__ x,
                                                  const float* __restrict__ skip,
                                                  const float* __restrict__ w_qkv)
{
    __shared__ float sx[64][64];
    __shared__ float ss[64][64];
    const int b  = blockIdx.y;
    const int n0 = blockIdx.x * 64;
    const int t  = threadIdx.x;

    for (int idx = t; idx < 64 * 64; idx += 256) {
        int c = idx >> 6, j = idx & 63;
        sx[c][j] = x[((b * 64 + c) << 12) + n0 + j];
        ss[c][j] = skip[((b * 64 + c) << 12) + n0 + j];
    }
    __syncthreads();

    const float scale = 0.125f;
    for (int r = 0; r < 48; r++) {
        int outIdx = t + (r << 8);
        int sel = outIdx >> 12;
        int rem = outIdx & 4095;
        int o = rem >> 6, j = rem & 63;
        const float* wrow = w_qkv + ((sel << 6) + o) * 64;
        float acc = 0.f;
        if (sel == 0) {
            #pragma unroll
            for (int c = 0; c < 64; c++) acc += wrow[c] * sx[c][j];
            g_q[(size_t)(((b << 12) + n0 + j) << 6) + o] = __float2bfloat16(acc * scale);
        } else {
            #pragma unroll
            for (int c = 0; c < 64; c++) acc += wrow[c] * ss[c][j];
            if (sel == 1) g_kT[(size_t)(((b << 12) + n0 + j) << 6) + o] = __float2bfloat16(acc);
            else          g_v [(size_t)(((b << 6) + o) << 12) + n0 + j] = __float2bfloat16(acc);
        }
    }
}

// ---------------- kernel 2: S = Q K^T -> bf16, 128n x 512m per CTA, cp.async 2-stage ----------------
__global__ __launch_bounds__(256) void scores_mma()
{
    __shared__ __align__(16) char sQ[128 * 128];       // 16 KB
    __shared__ __align__(16) char sK[2][128 * 128];    // 32 KB
    const int b = blockIdx.z, n0 = blockIdx.y * 128, mB = blockIdx.x * 512;
    const int t = threadIdx.x, wid = t >> 5, lane = t & 31;
    const uint32_t sQb = smem_u32(sQ);
    const uint32_t sKb0 = smem_u32(sK[0]);

    #pragma unroll
    for (int k = 0; k < 4; k++) {
        int i = t + k * 256;
        int r = i >> 3, q = i & 7;
        cp16(sQb + r * 128 + SWZ(r, q * 16),
             &g_q[(size_t)((b << 12) + n0 + r) * 64 + q * 8]);
        cp16(sKb0 + r * 128 + SWZ(r, q * 16),
             &g_kT[(size_t)((b << 12) + mB + r) * 64 + q * 8]);
    }
    CP_COMMIT();

    const int wn = wid >> 2, wm = wid & 3;   // warp tile: 64n x 32m
    const int gid = lane >> 2, tc = lane & 3;

    for (int mi = 0; mi < 4; mi++) {
        const uint32_t sKc = sKb0 + (mi & 1) * 16384;
        if (mi < 3) {
            const uint32_t sKn = sKb0 + ((mi + 1) & 1) * 16384;
            const int m0n = mB + (mi + 1) * 128;
            #pragma unroll
            for (int k = 0; k < 4; k++) {
                int i = t + k * 256;
                int r = i >> 3, q = i & 7;
                cp16(sKn + r * 128 + SWZ(r, q * 16),
                     &g_kT[(size_t)((b << 12) + m0n + r) * 64 + q * 8]);
            }
            CP_COMMIT();
            CP_WAIT(1);
        } else {
            CP_WAIT(0);
        }
        __syncthreads();

        float acc[4][4][4];
        #pragma unroll
        for (int i = 0; i < 4; i++)
            #pragma unroll
            for (int j = 0; j < 4; j++)
                #pragma unroll
                for (int e = 0; e < 4; e++) acc[i][j][e] = 0.f;

        #pragma unroll
        for (int ki = 0; ki < 4; ki++) {
            uint32_t afr[4][4], bfr[4][2];
            #pragma unroll
            for (int i = 0; i < 4; i++) {
                int row = wn * 64 + i * 16 + (lane & 15);
                int cb = ki * 32 + (lane >> 4) * 16;
                ldm_x4(afr[i], sQb + row * 128 + SWZ(row, cb));
            }
            #pragma unroll
            for (int j = 0; j < 4; j++) {
                int row = wm * 32 + j * 8 + (lane & 7);
                int cb = ki * 32 + ((lane >> 3) & 1) * 16;
                ldm_x2(bfr[j], sKc + row * 128 + SWZ(row, cb));
            }
            #pragma unroll
            for (int i = 0; i < 4; i++)
                #pragma unroll
                for (int j = 0; j < 4; j++)
                    mma_bf16(acc[i][j], afr[i], bfr[j]);
        }

        const int m0 = mB + mi * 128;
        #pragma unroll
        for (int i = 0; i < 4; i++) {
            int row = n0 + wn * 64 + i * 16 + gid;
            size_t r0 = ((size_t)b << 24) + (size_t)row * NTOK + m0 + wm * 32;
            size_t r1 = r0 + 8 * NTOK;
            #pragma unroll
            for (int j = 0; j < 4; j++) {
                *(unsigned*)&g_sb[r0 + j * 8 + tc * 2] = pack_bf16x2(acc[i][j][1], acc[i][j][0]);
                *(unsigned*)&g_sb[r1 + j * 8 + tc * 2] = pack_bf16x2(acc[i][j][3], acc[i][j][2]);
            }
        }
        __syncthreads();
    }
}

// ---------------- kernel 3: value-histogram top-k threshold + masked softmax, bf16 in/out ----------------
__global__ __launch_bounds__(256) void select_softmax_kernel()
{
    const int row = blockIdx.x;
    const int b = row >> 12, n = row & 4095;
    const size_t base = ((size_t)b << 24) + (size_t)n * NTOK;
    const int t = threadIdx.x;
    const int wid = t >> 5, lane = t & 31;

    __shared__ int hist8[8][256];
    __shared__ float candF[4096];
    __shared__ float warpMax[8], warpMin[8];
    __shared__ int warpTot[8];
    __shared__ int sh_cnt;
    __shared__ int sh_bin, sh_kk;
    __shared__ float sh_thr, sh_z;

    if (t == 0) { sh_cnt = 0; sh_z = 0.f; }
    #pragma unroll
    for (int w = 0; w < 8; w++) hist8[w][t] = 0;

    float vals[16];
    const size_t myb = base + (size_t)t * 16;
    #pragma unroll
    for (int h = 0; h < 2; h++) {
        uint4 raw = *(const uint4*)&g_sb[myb + h * 8];
        unsigned uw[4] = {raw.x, raw.y, raw.z, raw.w};
        #pragma unroll
        for (int j = 0; j < 4; j++) {
            vals[h * 8 + j * 2 + 0] = __uint_as_float(uw[j] << 16);
            vals[h * 8 + j * 2 + 1] = __uint_as_float(uw[j] & 0xffff0000u);
        }
    }

    float mymax = vals[0], mymin = vals[0];
    #pragma unroll
    for (int i = 1; i < 16; i++) {
        mymax = fmaxf(mymax, vals[i]);
        mymin = fminf(mymin, vals[i]);
    }
    #pragma unroll
    for (int off = 16; off; off >>= 1) {
        mymax = fmaxf(mymax, __shfl_xor_sync(0xffffffffu, mymax, off));
        mymin = fminf(mymin, __shfl_xor_sync(0xffffffffu, mymin, off));
    }
    if (lane == 0) { warpMax[wid] = mymax; warpMin[wid] = mymin; }
    __syncthreads();
    float rmax = warpMax[0], rmin = warpMin[0];
    #pragma unroll
    for (int w = 1; w < 8; w++) {
        rmax = fmaxf(rmax, warpMax[w]);
        rmin = fminf(rmin, warpMin[w]);
    }

    float range = rmax - rmin;
    float scale = 256.0f / (range + 1e-30f) * (1.0f - 1e-6f);
    int* myh = hist8[wid];
    int bins[16];
    #pragma unroll
    for (int i = 0; i < 16; i++) {
        int bin = (int)((vals[i] - rmin) * scale);
        bin = bin < 0 ? 0 : (bin > 255 ? 255 : bin);
        bins[i] = bin;
        atomicAdd(&myh[bin], 1);
    }
    __syncthreads();

    int tot = 0;
    #pragma unroll
    for (int w = 0; w < 8; w++) tot += hist8[w][t];
    int v = tot;
    #pragma unroll
    for (int off = 1; off < 32; off <<= 1) {
        int o = __shfl_down_sync(0xffffffffu, v, off);
        if (lane + off < 32) v += o;
    }
    if (lane == 0) warpTot[wid] = v;
    __syncthreads();
    int above = 0;
    #pragma unroll
    for (int w = 0; w < 8; w++) if (w > wid) above += warpTot[w];
    int cum_incl = v + above, cum_excl = cum_incl - tot;
    if (cum_excl < KSEL && KSEL <= cum_incl) { sh_bin = t; sh_kk = KSEL - cum_excl; }
    __syncthreads();
    const int selbin = sh_bin;
    const int kk = sh_kk;

    {
        int cnt = 0;
        #pragma unroll
        for (int i = 0; i < 16; i++) cnt += (bins[i] == selbin);
        int pos = 0;
        if (cnt) pos = atomicAdd(&sh_cnt, cnt);
        #pragma unroll
        for (int i = 0; i < 16; i++)
            if (bins[i] == selbin) candF[pos++] = vals[i];
    }
    __syncthreads();
    const int ncand = sh_cnt;

    for (int i = t; i < ncand; i += 256) {
        float xx = candF[i];
        int gt = 0, eq = 0;
        for (int j = 0; j < ncand; j++) {
            float y = candF[j];
            gt += (y > xx);
            eq += (y == xx);
        }
        if (gt < kk && kk <= gt + eq) sh_thr = xx;
    }
    __syncthreads();

    const float thr = sh_thr;
    const float M = fmaxf(rmax, 0.f);
    const float expM = __expf(-M);

    float w[16];
    float zloc = 0.f;
    #pragma unroll
    for (int i = 0; i < 16; i++) {
        float wv = (vals[i] >= thr) ? __expf(vals[i] - M) : expM;
        w[i] = wv;
        zloc += wv;
    }
    #pragma unroll
    for (int off = 16; off; off >>= 1) zloc += __shfl_xor_sync(0xffffffffu, zloc, off);
    if (lane == 0) atomicAdd(&sh_z, zloc);
    __syncthreads();

    float invZ = 1.f / sh_z;
    #pragma unroll
    for (int h = 0; h < 2; h++) {
        uint4 o;
        o.x = pack_bf16x2(w[h*8+1] * invZ, w[h*8+0] * invZ);
        o.y = pack_bf16x2(w[h*8+3] * invZ, w[h*8+2] * invZ);
        o.z = pack_bf16x2(w[h*8+5] * invZ, w[h*8+4] * invZ);
        o.w = pack_bf16x2(w[h*8+7] * invZ, w[h*8+6] * invZ);
        *(uint4*)&g_p[myb + h * 8] = o;
    }
}

// ---------------- kernel 4: O(n,c) = P V^T, 64n x 64c per CTA, cp.async 3-stage ----------------
__global__ __launch_bounds__(256) void av_mma()
{
    __shared__ __align__(16) char sP[3][64 * 128];   // 24 KB
    __shared__ __align__(16) char sV[3][64 * 128];   // 24 KB
    const int b = blockIdx.y, n0 = blockIdx.x * 64;
    const int t = threadIdx.x, wid = t >> 5, lane = t & 31;
    const uint32_t sPb0 = smem_u32(sP[0]), sVb0 = smem_u32(sV[0]);
    const size_t pb = ((size_t)b << 24);

    // preload chunks 0, 1
    #pragma unroll
    for (int c0 = 0; c0 < 2; c0++) {
        const uint32_t sPn = sPb0 + c0 * 8192;
        const uint32_t sVn = sVb0 + c0 * 8192;
        const int mb = c0 * 64;
        #pragma unroll
        for (int k = 0; k < 2; k++) {
            int i = t + k * 256;
            int r = i >> 3, q = i & 7;
            cp16(sPn + r * 128 + SWZ(r, q * 16),
                 &g_p[pb + (size_t)(n0 + r) * NTOK + mb + q * 8]);
            cp16(sVn + r * 128 + SWZ(r, q * 16),
                 &g_v[(size_t)(((b << 6) + r) << 12) + mb + q * 8]);
        }
        CP_COMMIT();
    }

    const int wn = wid >> 2, wc = wid & 3;   // warp tile: 32n x 16c
    float acc[2][2][4];
    #pragma unroll
    for (int i = 0; i < 2; i++)
        #pragma unroll
        for (int j = 0; j < 2; j++)
            #pragma unroll
            for (int e = 0; e < 4; e++) acc[i][j][e] = 0.f;

    int cur = 0, nxt = 2;
    for (int mt = 0; mt < 64; mt++) {
        if (mt < 62) {
            const int mb = (mt + 2) * 64;
            const uint32_t sPn = sPb0 + nxt * 8192;
            const uint32_t sVn = sVb0 + nxt * 8192;
            #pragma unroll
            for (int k = 0; k < 2; k++) {
                int i = t + k * 256;
                int r = i >> 3, q = i & 7;
                cp16(sPn + r * 128 + SWZ(r, q * 16),
                     &g_p[pb + (size_t)(n0 + r) * NTOK + mb + q * 8]);
                cp16(sVn + r * 128 + SWZ(r, q * 16),
                     &g_v[(size_t)(((b << 6) + r) << 12) + mb + q * 8]);
            }
            CP_COMMIT();
            CP_WAIT(2);
            nxt = nxt + 1 == 3 ? 0 : nxt + 1;
        } else {
            CP_WAIT(0);
        }
        __syncthreads();

        const uint32_t sPc = sPb0 + cur * 8192;
        const uint32_t sVc = sVb0 + cur * 8192;
        #pragma unroll
        for (int ki = 0; ki < 4; ki++) {
            uint32_t afr[2][4], bfr[2][2];
            #pragma unroll
            for (int i = 0; i < 2; i++) {
                int row = wn * 32 + i * 16 + (lane & 15);
                int cb = ki * 32 + (lane >> 4) * 16;
                ldm_x4(afr[i], sPc + row * 128 + SWZ(row, cb));
            }
            #pragma unroll
            for (int j = 0; j < 2; j++) {
                int row = wc * 16 + j * 8 + (lane & 7);
                int cb = ki * 32 + ((lane >> 3) & 1) * 16;
                ldm_x2(bfr[j], sVc + row * 128 + SWZ(row, cb));
            }
            #pragma unroll
            for (int i = 0; i < 2; i++)
                #pragma unroll
                for (int j = 0; j < 2; j++)
                    mma_bf16(acc[i][j], afr[i], bfr[j]);
        }
        __syncthreads();
        cur = cur + 1 == 3 ? 0 : cur + 1;
    }

    const int gid = lane >> 2, tc = lane & 3;
    #pragma unroll
    for (int i = 0; i < 2; i++) {
        int row = n0 + wn * 32 + i * 16 + gid;
        size_t r0 = (size_t)((b << 12) + row) * 64 + wc * 16;
        size_t r1 = r0 + 8 * 64;
        #pragma unroll
        for (int j = 0; j < 2; j++) {
            *(float2*)&g_o[r0 + j * 8 + tc * 2] = make_float2(acc[i][j][0], acc[i][j][1]);
            *(float2*)&g_o[r1 + j * 8 + tc * 2] = make_float2(acc[i][j][2], acc[i][j][3]);
        }
    }
}

// ---------------- kernel 5: output projection + bias + residual ----------------
__global__ __launch_bounds__(256) void proj_kernel(const float* __restrict__ x,
                                                   const float* __restrict__ w_out,
                                                   const float* __restrict__ b_out,
                                                   const float* __restrict__ gamma,
                                                   float* __restrict__ out)
{
    __shared__ float sT[64][65];
    const int b  = blockIdx.y;
    const int n0 = blockIdx.x * 64;
    const int t  = threadIdx.x;

    for (int idx = t; idx < 64 * 64; idx += 256) {
        int j = idx >> 6, c = idx & 63;
        sT[c][j] = g_o[(size_t)((b << 12) + n0 + j) * 64 + c];
    }
    __syncthreads();

    const float g = gamma[0];
    for (int r = 0; r < 16; r++) {
        int outIdx = t + (r << 8);
        int o = outIdx >> 6, j = outIdx & 63;
        const float* wrow = w_out + o * 64;
        float acc = b_out[o];
        #pragma unroll
        for (int c = 0; c < 64; c++) acc += wrow[c] * sT[c][j];
        size_t gi = (size_t)(((b << 6) + o) << 12) + n0 + j;
        out[gi] = g * acc + x[gi];
    }
}

// ---------------- launch ----------------
extern "C" void kernel_launch(void* const* d_in, const int* in_sizes, int n_in,
                              void* d_out, int out_size)
{
    const float* x     = (const float*)d_in[0];
    const float* skip  = (const float*)d_in[1];
    const float* w_qkv = (const float*)d_in[2];
    const float* w_out = (const float*)d_in[3];
    const float* b_out = (const float*)d_in[4];
    const float* gamma = (const float*)d_in[5];
    float* out = (float*)d_out;

    qkv_kernel<<<dim3(64, BATCH), 256>>>(x, skip, w_qkv);
    scores_mma<<<dim3(8, 32, BATCH), 256>>>();
    select_softmax_kernel<<<BATCH * NTOK, 256>>>();
    av_mma<<<dim3(64, BATCH), 256>>>();
    proj_kernel<<<dim3(64, BATCH), 256>>>(x, w_out, b_out, gamma, out);
}